// round 1
// baseline (speedup 1.0000x reference)
#include <cuda_runtime.h>
#include <math.h>

// Problem constants
#define TPB 256
constexpr int CDIM  = 128;
constexpr int WSZ   = 7;
constexpr int TOK   = 49;     // WSZ*WSZ
constexpr int NH    = 8;
constexpr int HD    = 16;
constexpr int HIMG  = 56;
constexpr int NPIX  = 3136;   // 56*56
constexpr float SCALE_F = 0.25f;   // HD^-0.5
constexpr float LN_EPS  = 1e-5f;

// Shared memory layout (floats)
constexpr int SXS      = 129;                 // sX row stride (odd -> conflict-free)
constexpr int SX_F     = 64 * SXS;            // 8256
constexpr int SB_F     = 128 * 64;            // 8192 (B chunk, k-major [128][64])
constexpr int SQKV_OFF = SX_F + SB_F;         // 16448
constexpr int SMEM_F   = SQKV_OFF + 64 * 384; // 41024 floats = 164096 bytes
// Phase-C per-warp scratch (reuses sX+sB region): K(49x17) + V(49x17) + P(49)
constexpr int KVW = 1728;                     // per-warp floats; 8*1728=13824 < 16448

__device__ __forceinline__ void gemm_tile_128(const float* __restrict__ sA, int lda,
                                              const float* __restrict__ sB,
                                              int ty, int tx, float acc[4][4]) {
    #pragma unroll 4
    for (int k = 0; k < 128; ++k) {
        float a0 = sA[(ty     ) * lda + k];
        float a1 = sA[(ty + 16) * lda + k];
        float a2 = sA[(ty + 32) * lda + k];
        float a3 = sA[(ty + 48) * lda + k];
        float b0 = sB[k * 64 + tx     ];
        float b1 = sB[k * 64 + tx + 16];
        float b2 = sB[k * 64 + tx + 32];
        float b3 = sB[k * 64 + tx + 48];
        acc[0][0] += a0 * b0; acc[0][1] += a0 * b1; acc[0][2] += a0 * b2; acc[0][3] += a0 * b3;
        acc[1][0] += a1 * b0; acc[1][1] += a1 * b1; acc[1][2] += a1 * b2; acc[1][3] += a1 * b3;
        acc[2][0] += a2 * b0; acc[2][1] += a2 * b1; acc[2][2] += a2 * b2; acc[2][3] += a2 * b3;
        acc[3][0] += a3 * b0; acc[3][1] += a3 * b1; acc[3][2] += a3 * b2; acc[3][3] += a3 * b3;
    }
}

__global__ __launch_bounds__(TPB, 1)
void swin_window_attn_kernel(const float* __restrict__ x,
                             const float* __restrict__ ln_g,
                             const float* __restrict__ ln_b,
                             const float* __restrict__ wqkv,
                             const float* __restrict__ bqkv,
                             const float* __restrict__ wout,
                             const float* __restrict__ bout,
                             float* __restrict__ out) {
    extern __shared__ float sm[];
    float* sX   = sm;              // [64][129] normalized input (rows 49..63 zero)
    float* sB   = sm + SX_F;       // [128][64] weight chunk, k-major
    float* sQKV = sm + SQKV_OFF;   // [64][384] qkv, then attn-out in cols [0,128)

    const int tid  = threadIdx.x;
    const int wid  = tid >> 5;
    const int lane = tid & 31;
    const int w    = blockIdx.x;
    const int b    = w >> 6;
    const int wy   = (w >> 3) & 7;
    const int wx   = w & 7;

    // ---------------- Phase A: LayerNorm (warp per token) ----------------
    {
        float4 gg = *reinterpret_cast<const float4*>(&ln_g[lane * 4]);
        float4 bb = *reinterpret_cast<const float4*>(&ln_b[lane * 4]);
        for (int t = wid; t < TOK; t += 8) {
            int r    = wy * WSZ + t / WSZ;
            int cpos = wx * WSZ + t % WSZ;
            const float* xr = x + (size_t)(b * NPIX + r * HIMG + cpos) * CDIM;
            float4 v = *reinterpret_cast<const float4*>(&xr[lane * 4]);
            float s = v.x + v.y + v.z + v.w;
            float q = v.x * v.x + v.y * v.y + v.z * v.z + v.w * v.w;
            #pragma unroll
            for (int off = 16; off; off >>= 1) {
                s += __shfl_xor_sync(0xffffffffu, s, off);
                q += __shfl_xor_sync(0xffffffffu, q, off);
            }
            float mu  = s * (1.f / 128.f);
            float var = q * (1.f / 128.f) - mu * mu;
            float rs  = rsqrtf(var + LN_EPS);
            float* dst = &sX[t * SXS + lane * 4];
            dst[0] = (v.x - mu) * rs * gg.x + bb.x;
            dst[1] = (v.y - mu) * rs * gg.y + bb.y;
            dst[2] = (v.z - mu) * rs * gg.z + bb.z;
            dst[3] = (v.w - mu) * rs * gg.w + bb.w;
        }
        // zero pad rows 49..63 of sX (GEMM reads 64 rows)
        for (int p = tid; p < 15 * SXS; p += TPB) sX[TOK * SXS + p] = 0.f;
    }

    const int ty = tid >> 4;  // 0..15 : M dimension
    const int tx = tid & 15;  // 0..15 : N dimension

    // ---------------- Phase B: QKV GEMM [64x384] = sX[64x128] @ wqkv[128x384] ----------------
    for (int ch = 0; ch < 6; ++ch) {
        __syncthreads();  // previous consumers of sB done / sX ready on first iter
        for (int p = tid * 4; p < 8192; p += TPB * 4) {
            int k = p >> 6, j = p & 63;
            *reinterpret_cast<float4*>(&sB[p]) =
                *reinterpret_cast<const float4*>(&wqkv[k * 384 + ch * 64 + j]);
        }
        __syncthreads();
        float acc[4][4] = {};
        gemm_tile_128(sX, SXS, sB, ty, tx, acc);
        #pragma unroll
        for (int j = 0; j < 4; ++j) {
            float bv = bqkv[ch * 64 + tx + 16 * j];
            #pragma unroll
            for (int i = 0; i < 4; ++i)
                sQKV[(ty + 16 * i) * 384 + ch * 64 + tx + 16 * j] = acc[i][j] + bv;
        }
    }
    __syncthreads();

    // ---------------- Phase C: attention, warp `wid` owns head `wid` ----------------
    {
        float* sK = sm + wid * KVW;   // [49][17]
        float* sV = sK + 833;         // [49][17]
        float* sP = sK + 1666;        // [49] exp(scores) row buffer
        for (int p = lane; p < TOK * HD; p += 32) {
            int t = p >> 4, d = p & 15;
            sK[t * 17 + d] = sQKV[t * 384 + 128 + wid * 16 + d];
            sV[t * 17 + d] = sQKV[t * 384 + 256 + wid * 16 + d];
        }
        __syncwarp();
        const int dd = lane & 15, h2 = lane >> 4;
        for (int qt = 0; qt < TOK; ++qt) {
            const float* qrow = &sQKV[qt * 384 + wid * 16];
            float s0 = 0.f, s1 = 0.f;
            #pragma unroll
            for (int d = 0; d < 16; ++d) {
                float qv = qrow[d];
                s0 += qv * sK[lane * 17 + d];           // kt = lane (0..31, all < 49)
                s1 += qv * sK[(lane + 32) * 17 + d];    // kt = lane+32 (valid if lane<17)
            }
            s0 *= SCALE_F; s1 *= SCALE_F;
            float mval = (lane < 17) ? fmaxf(s0, s1) : s0;
            #pragma unroll
            for (int off = 16; off; off >>= 1)
                mval = fmaxf(mval, __shfl_xor_sync(0xffffffffu, mval, off));
            float e0 = __expf(s0 - mval);
            float e1 = (lane < 17) ? __expf(s1 - mval) : 0.f;
            float ssum = e0 + e1;
            #pragma unroll
            for (int off = 16; off; off >>= 1)
                ssum += __shfl_xor_sync(0xffffffffu, ssum, off);
            float inv = __frcp_rn(ssum);
            sP[lane] = e0;
            if (lane < 17) sP[lane + 32] = e1;
            __syncwarp();
            // O[qt][dd] = sum_kt P[kt] * V[kt][dd]; lanes split kt by parity (h2)
            float oacc = 0.f;
            #pragma unroll
            for (int i = 0; i < 25; ++i) {
                int kt = 2 * i + h2;
                if (kt < TOK) oacc += sP[kt] * sV[kt * 17 + dd];
            }
            oacc += __shfl_xor_sync(0xffffffffu, oacc, 16);
            // overwrite q-slot of this head with attention output (q[qt] no longer needed)
            if (lane < 16) sQKV[qt * 384 + wid * 16 + dd] = oacc * inv;
            __syncwarp();
        }
    }
    __syncthreads();

    // ---------------- Phase D: out projection [49x128] = attn[49x128] @ wout[128x128] ----------------
    for (int ch = 0; ch < 2; ++ch) {
        for (int p = tid * 4; p < 8192; p += TPB * 4) {
            int k = p >> 6, j = p & 63;
            *reinterpret_cast<float4*>(&sB[p]) =
                *reinterpret_cast<const float4*>(&wout[k * 128 + ch * 64 + j]);
        }
        __syncthreads();
        float acc[4][4] = {};
        gemm_tile_128(sQKV, 384, sB, ty, tx, acc);
        #pragma unroll
        for (int i = 0; i < 4; ++i) {
            int m = ty + 16 * i;
            if (m < TOK) {
                int r    = wy * WSZ + m / WSZ;
                int cpos = wx * WSZ + m % WSZ;
                float* orow = out + (size_t)(b * NPIX + r * HIMG + cpos) * CDIM + ch * 64;
                #pragma unroll
                for (int j = 0; j < 4; ++j)
                    orow[tx + 16 * j] = acc[i][j] + bout[ch * 64 + tx + 16 * j];
            }
        }
        __syncthreads();  // sB consumers done before next chunk overwrites
    }
}

extern "C" void kernel_launch(void* const* d_in, const int* in_sizes, int n_in,
                              void* d_out, int out_size) {
    const float* x    = (const float*)d_in[0];
    const float* g    = (const float*)d_in[1];
    const float* bt   = (const float*)d_in[2];
    const float* wqkv = (const float*)d_in[3];
    const float* bqkv = (const float*)d_in[4];
    const float* wout = (const float*)d_in[5];
    const float* bout = (const float*)d_in[6];
    float* out = (float*)d_out;

    const int smem_bytes = SMEM_F * (int)sizeof(float);  // 164096
    cudaFuncSetAttribute(swin_window_attn_kernel,
                         cudaFuncAttributeMaxDynamicSharedMemorySize, smem_bytes);
    swin_window_attn_kernel<<<4096, TPB, smem_bytes>>>(x, g, bt, wqkv, bqkv, wout, bout, out);
}

// round 2
// speedup vs baseline: 1.3945x; 1.3945x over previous
#include <cuda_runtime.h>
#include <math.h>

#define TPB 256
constexpr int CDIM  = 128;
constexpr int WSZ   = 7;
constexpr int TOK   = 49;
constexpr int HIMG  = 56;
constexpr int NPIX  = 3136;
constexpr float SCALE_F = 0.25f;
constexpr float LN_EPS  = 1e-5f;

// Shared memory layout (floats)
constexpr int SXS      = 132;                 // sX row stride (float4-aligned, conflict-irrelevant: broadcast reads)
constexpr int SX_F     = 64 * SXS;            // 8448
constexpr int SB_F     = 128 * 128;           // 16384 (weight chunk, k-major [128][128])
constexpr int SQKV_OFF = SX_F + SB_F;         // 24832
constexpr int SMEM_F   = SQKV_OFF + 64 * 384; // 49408 floats = 197632 bytes
// Phase-C per-warp scratch overlays sX+sB region: K(49x18) + V(49x18) + P(49)
constexpr int KVW = 1824;                     // 8*1824 = 14592 < 24832

using u64 = unsigned long long;
__device__ __forceinline__ u64 pk2(float lo, float hi) {
    u64 r; asm("mov.b64 %0,{%1,%2};" : "=l"(r) : "f"(lo), "f"(hi)); return r;
}
__device__ __forceinline__ void fma2(u64& d, u64 a, u64 b) {
    asm("fma.rn.f32x2 %0,%1,%2,%3;" : "=l"(d) : "l"(a), "l"(b), "l"(d));
}
__device__ __forceinline__ void upk2(u64 v, float& lo, float& hi) {
    asm("mov.b64 {%0,%1},%2;" : "=f"(lo), "=f"(hi) : "l"(v));
}

// C[64x128] += A[64x128] @ B[128x128]; A k-major stride lda, B k-major [k][128].
// Thread tile: 8 rows (rowg = tid>>5) x 4 cols as 2 f32x2 (colg = tid&31).
__device__ __forceinline__ void gemm64x128_f32x2(const float* __restrict__ sA, int lda,
                                                 const float* __restrict__ sB,
                                                 int rowg, int colg, u64 acc[8][2]) {
    const float* aBase = sA + rowg * 8 * lda;
    const float* bBase = sB + colg * 4;
    #pragma unroll 4
    for (int k0 = 0; k0 < 128; k0 += 4) {
        float4 rA[8];
        #pragma unroll
        for (int i = 0; i < 8; ++i)
            rA[i] = *reinterpret_cast<const float4*>(&aBase[i * lda + k0]);
        #pragma unroll
        for (int kk = 0; kk < 4; ++kk) {
            float4 b = *reinterpret_cast<const float4*>(&bBase[(k0 + kk) * 128]);
            u64 b01 = pk2(b.x, b.y), b23 = pk2(b.z, b.w);
            #pragma unroll
            for (int i = 0; i < 8; ++i) {
                float a = reinterpret_cast<const float*>(&rA[i])[kk];
                u64 a2 = pk2(a, a);
                fma2(acc[i][0], a2, b01);
                fma2(acc[i][1], a2, b23);
            }
        }
    }
}

__global__ __launch_bounds__(TPB, 1)
void swin_window_attn_kernel(const float* __restrict__ x,
                             const float* __restrict__ ln_g,
                             const float* __restrict__ ln_b,
                             const float* __restrict__ wqkv,
                             const float* __restrict__ bqkv,
                             const float* __restrict__ wout,
                             const float* __restrict__ bout,
                             float* __restrict__ out) {
    extern __shared__ float sm[];
    float* sX   = sm;              // [64][132] normalized input (rows 49..63 zero)
    float* sB   = sm + SX_F;       // [128][128] weight chunk, k-major
    float* sQKV = sm + SQKV_OFF;   // [64][384] qkv; attn-out overwrites cols [0,128)

    const int tid  = threadIdx.x;
    const int wid  = tid >> 5;
    const int lane = tid & 31;
    const int w    = blockIdx.x;
    const int b    = w >> 6;
    const int wy   = (w >> 3) & 7;
    const int wx   = w & 7;

    // ---------------- Phase A: LayerNorm (warp per token) ----------------
    {
        float4 gg = *reinterpret_cast<const float4*>(&ln_g[lane * 4]);
        float4 bb = *reinterpret_cast<const float4*>(&ln_b[lane * 4]);
        for (int t = wid; t < TOK; t += 8) {
            int r    = wy * WSZ + t / WSZ;
            int cpos = wx * WSZ + t % WSZ;
            const float* xr = x + (size_t)(b * NPIX + r * HIMG + cpos) * CDIM;
            float4 v = *reinterpret_cast<const float4*>(&xr[lane * 4]);
            float s = v.x + v.y + v.z + v.w;
            float q = v.x * v.x + v.y * v.y + v.z * v.z + v.w * v.w;
            #pragma unroll
            for (int off = 16; off; off >>= 1) {
                s += __shfl_xor_sync(0xffffffffu, s, off);
                q += __shfl_xor_sync(0xffffffffu, q, off);
            }
            float mu  = s * (1.f / 128.f);
            float var = q * (1.f / 128.f) - mu * mu;
            float rs  = rsqrtf(var + LN_EPS);
            float* dst = &sX[t * SXS + lane * 4];
            float4 o;
            o.x = (v.x - mu) * rs * gg.x + bb.x;
            o.y = (v.y - mu) * rs * gg.y + bb.y;
            o.z = (v.z - mu) * rs * gg.z + bb.z;
            o.w = (v.w - mu) * rs * gg.w + bb.w;
            *reinterpret_cast<float4*>(dst) = o;
        }
        for (int p = tid; p < 15 * SXS; p += TPB) sX[TOK * SXS + p] = 0.f;
    }

    const int rowg = tid >> 5;   // 0..7 : 8 rows each
    const int colg = tid & 31;   // 0..31 : 4 cols each

    // ---------------- Phase B: QKV GEMM [64x384] = sX @ wqkv, 3 chunks of N=128 ----------------
    for (int ch = 0; ch < 3; ++ch) {
        __syncthreads();
        for (int f = tid; f < 4096; f += TPB) {
            int k = f >> 5, j = f & 31;
            *reinterpret_cast<float4*>(&sB[k * 128 + j * 4]) =
                *reinterpret_cast<const float4*>(&wqkv[k * 384 + ch * 128 + j * 4]);
        }
        __syncthreads();
        u64 acc[8][2] = {};
        gemm64x128_f32x2(sX, SXS, sB, rowg, colg, acc);
        float4 bv = *reinterpret_cast<const float4*>(&bqkv[ch * 128 + colg * 4]);
        #pragma unroll
        for (int i = 0; i < 8; ++i) {
            float x0, x1, y0, y1;
            upk2(acc[i][0], x0, x1);
            upk2(acc[i][1], y0, y1);
            *reinterpret_cast<float4*>(&sQKV[(rowg * 8 + i) * 384 + ch * 128 + colg * 4]) =
                make_float4(x0 + bv.x, x1 + bv.y, y0 + bv.z, y1 + bv.w);
        }
    }
    __syncthreads();

    // ---------------- Phase C: attention, warp `wid` owns head `wid` ----------------
    {
        float* sK = sm + wid * KVW;   // [49][18]
        float* sV = sK + 882;         // [49][18]
        float* sP = sK + 1764;        // [49]
        for (int p = lane; p < TOK * 16; p += 32) {
            int t = p >> 4, d = p & 15;
            sK[t * 18 + d] = sQKV[t * 384 + 128 + wid * 16 + d];
            sV[t * 18 + d] = sQKV[t * 384 + 256 + wid * 16 + d];
        }
        __syncwarp();
        const int dp = lane & 7, h4 = lane >> 3;
        const u64* k0p = reinterpret_cast<const u64*>(&sK[lane * 18]);
        const u64* k1p = reinterpret_cast<const u64*>(&sK[(lane + 32) * 18]);  // may read junk; gated below
        for (int qt = 0; qt < TOK; ++qt) {
            const float* qrow = &sQKV[qt * 384 + wid * 16];
            const u64* q2 = reinterpret_cast<const u64*>(qrow);
            u64 a0 = 0ull, a1 = 0ull;
            #pragma unroll
            for (int j = 0; j < 8; ++j) {
                u64 qv = q2[j];
                fma2(a0, qv, k0p[j]);
                fma2(a1, qv, k1p[j]);
            }
            float s0a, s0b, s1a, s1b;
            upk2(a0, s0a, s0b);
            upk2(a1, s1a, s1b);
            float e0 = __expf((s0a + s0b) * SCALE_F);                       // kt = lane (<49)
            float e1 = (lane < 17) ? __expf((s1a + s1b) * SCALE_F) : 0.f;   // kt = lane+32
            float ssum = e0 + e1;
            #pragma unroll
            for (int off = 16; off; off >>= 1)
                ssum += __shfl_xor_sync(0xffffffffu, ssum, off);
            float inv = __frcp_rn(ssum);
            sP[lane] = e0;
            if (lane < 17) sP[lane + 32] = e1;
            __syncwarp();
            // O[qt][2dp..2dp+1]: lanes split kt mod 4 via h4, 13 iters of FFMA2
            u64 o2 = 0ull;
            #pragma unroll
            for (int i = 0; i < 13; ++i) {
                int kt = h4 + 4 * i;
                if (kt < TOK) {
                    float p = sP[kt];
                    u64 v2 = *reinterpret_cast<const u64*>(&sV[kt * 18 + 2 * dp]);
                    fma2(o2, pk2(p, p), v2);
                }
            }
            float olo, ohi;
            upk2(o2, olo, ohi);
            olo += __shfl_xor_sync(0xffffffffu, olo, 8);
            ohi += __shfl_xor_sync(0xffffffffu, ohi, 8);
            olo += __shfl_xor_sync(0xffffffffu, olo, 16);
            ohi += __shfl_xor_sync(0xffffffffu, ohi, 16);
            if (lane < 8)
                *reinterpret_cast<float2*>(&sQKV[qt * 384 + wid * 16 + 2 * dp]) =
                    make_float2(olo * inv, ohi * inv);
            __syncwarp();
        }
    }
    __syncthreads();

    // ---------------- Phase D: out projection [49x128] = attn[64x128] @ wout[128x128] ----------------
    {
        for (int f = tid; f < 4096; f += TPB) {
            int k = f >> 5, j = f & 31;
            *reinterpret_cast<float4*>(&sB[k * 128 + j * 4]) =
                *reinterpret_cast<const float4*>(&wout[k * 128 + j * 4]);
        }
        __syncthreads();
        u64 acc[8][2] = {};
        gemm64x128_f32x2(sQKV, 384, sB, rowg, colg, acc);
        float4 bo = *reinterpret_cast<const float4*>(&bout[colg * 4]);
        #pragma unroll
        for (int i = 0; i < 8; ++i) {
            int m = rowg * 8 + i;
            if (m < TOK) {
                int r    = wy * WSZ + m / WSZ;
                int cpos = wx * WSZ + m % WSZ;
                float x0, x1, y0, y1;
                upk2(acc[i][0], x0, x1);
                upk2(acc[i][1], y0, y1);
                *reinterpret_cast<float4*>(
                    out + (size_t)(b * NPIX + r * HIMG + cpos) * CDIM + colg * 4) =
                    make_float4(x0 + bo.x, x1 + bo.y, y0 + bo.z, y1 + bo.w);
            }
        }
    }
}

extern "C" void kernel_launch(void* const* d_in, const int* in_sizes, int n_in,
                              void* d_out, int out_size) {
    const float* x    = (const float*)d_in[0];
    const float* g    = (const float*)d_in[1];
    const float* bt   = (const float*)d_in[2];
    const float* wqkv = (const float*)d_in[3];
    const float* bqkv = (const float*)d_in[4];
    const float* wout = (const float*)d_in[5];
    const float* bout = (const float*)d_in[6];
    float* out = (float*)d_out;

    const int smem_bytes = SMEM_F * (int)sizeof(float);  // 197632
    cudaFuncSetAttribute(swin_window_attn_kernel,
                         cudaFuncAttributeMaxDynamicSharedMemorySize, smem_bytes);
    swin_window_attn_kernel<<<4096, TPB, smem_bytes>>>(x, g, bt, wqkv, bqkv, wout, bout, out);
}